// round 4
// baseline (speedup 1.0000x reference)
#include <cuda_runtime.h>
#include <math.h>

#define BATCH 4
#define CDIM  64
#define HWD   4096
#define CHW   (CDIM*HWD)

typedef unsigned long long u64;

// ---------------- scratch (device globals; no allocation allowed) ----------------
__device__ __align__(16) float g_xn[BATCH*CHW];
__device__ __align__(16) float g_q0[BATCH*8*HWD];
__device__ __align__(16) float g_k0[BATCH*8*HWD];
__device__ __align__(16) float g_v0[BATCH*CHW];
__device__ __align__(16) float g_qq[BATCH*8*HWD];
__device__ __align__(16) float g_kk[BATCH*8*HWD];
__device__ __align__(16) float g_vv[BATCH*CHW];
__device__ __align__(16) float g_ao[BATCH*CHW];
__device__ __align__(16) float g_sa[BATCH*CHW];
__device__ __align__(16) float g_c1[BATCH*21*HWD];
__device__ __align__(16) float g_cy[BATCH*CHW];
__device__ float g_pool[BATCH*CDIM];
__device__ float g_pm[BATCH*CDIM];
__device__ __align__(16) float g_fs[BATCH*CHW];

// ---------------- helpers ----------------
__device__ __forceinline__ u64 pack2(float lo, float hi){
  u64 r; asm("mov.b64 %0,{%1,%2};" : "=l"(r) : "f"(lo), "f"(hi)); return r;
}
__device__ __forceinline__ void unpack2(u64 v, float& lo, float& hi){
  asm("mov.b64 {%0,%1},%2;" : "=f"(lo), "=f"(hi) : "l"(v));
}
__device__ __forceinline__ u64 ffma2(u64 a, u64 b, u64 c){
  u64 d; asm("fma.rn.f32x2 %0,%1,%2,%3;" : "=l"(d) : "l"(a), "l"(b), "l"(c)); return d;
}
__device__ __forceinline__ u64 fadd2(u64 a, u64 b){
  u64 d; asm("add.rn.f32x2 %0,%1,%2;" : "=l"(d) : "l"(a), "l"(b)); return d;
}
__device__ __forceinline__ float gelu_f(float x){
  return 0.5f*x*(1.0f + erff(x*0.7071067811865476f));
}

// ---------------- LayerNorm over channel dim (per pixel) ----------------
__global__ __launch_bounds__(256) void ln_kernel(const float* __restrict__ x,
    const float* __restrict__ w, const float* __restrict__ bia){
  __shared__ float xs[64*64];
  __shared__ float mu[64], rs[64];
  int b = blockIdx.y, p0 = blockIdx.x*64, tid = threadIdx.x;
  const float* xb = x + (size_t)b*CHW + p0;
  for (int i=tid;i<4096;i+=256){int c=i>>6,p=i&63; xs[i]=xb[c*HWD+p];}
  __syncthreads();
  if (tid<64){
    float s=0.f,s2=0.f;
    #pragma unroll
    for (int c=0;c<64;c++){float v=xs[c*64+tid]; s+=v; s2+=v*v;}
    float m=s*(1.f/64.f);
    mu[tid]=m; rs[tid]=rsqrtf(s2*(1.f/64.f)-m*m+1e-5f);
  }
  __syncthreads();
  float* ob = g_xn + (size_t)b*CHW + p0;
  for (int i=tid;i<4096;i+=256){int c=i>>6,p=i&63;
    ob[c*HWD+p]=(xs[i]-mu[p])*rs[p]*w[c]+bia[c];}
}

// ---------------- fused q/k/v 1x1 convs (80 output channels) ----------------
__global__ __launch_bounds__(256) void qkv_kernel(
    const float* __restrict__ qw, const float* __restrict__ qb,
    const float* __restrict__ kw, const float* __restrict__ kb,
    const float* __restrict__ vw, const float* __restrict__ vb){
  __shared__ float ws[80*64];
  __shared__ float bs[80];
  __shared__ float xs[64*64];
  int b = blockIdx.y, p0 = blockIdx.x*64, tid = threadIdx.x;
  for (int t=tid;t<80*64;t+=256){
    int o=t>>6, i=t&63;
    ws[t] = (o<8)? qw[o*64+i] : (o<16)? kw[(o-8)*64+i] : vw[(o-16)*64+i];
  }
  if (tid<80) bs[tid] = (tid<8)? qb[tid] : (tid<16)? kb[tid-8] : vb[tid-16];
  const float* xb = g_xn + (size_t)b*CHW + p0;
  for (int i=tid;i<4096;i+=256){int c=i>>6,p=i&63; xs[i]=xb[c*HWD+p];}
  __syncthreads();
  int og=tid>>6, p=tid&63;
  for (int r=0;r<20;r++){
    int o=og*20+r;
    float acc=bs[o];
    #pragma unroll
    for (int i=0;i<64;i++) acc += ws[o*64+i]*xs[i*64+p];
    float* dst = (o<8)? (g_q0 + ((size_t)b*8+o)*HWD)
               : (o<16)? (g_k0 + ((size_t)b*8+(o-8))*HWD)
               : (g_v0 + ((size_t)b*64+(o-16))*HWD);
    dst[p0+p]=acc;
  }
}

// ---------------- depthwise 3x3 (q:8, k:8, v:64 channels) ----------------
__global__ __launch_bounds__(256) void dw_kernel(
    const float* __restrict__ qkw, const float* __restrict__ qkb,
    const float* __restrict__ vw, const float* __restrict__ vb){
  int idx = blockIdx.x*256 + threadIdx.x;   // B*80*HWD total
  int p  = idx & 4095;
  int ch = (idx>>12) % 80;
  int b  = (idx>>12) / 80;
  const float* src; const float* wt; float bias; float* dst;
  if (ch<8){ src=g_q0+((size_t)b*8+ch)*HWD;  wt=qkw+ch*9;      bias=qkb[ch];     dst=g_qq+((size_t)b*8+ch)*HWD; }
  else if (ch<16){ int c2=ch-8;  src=g_k0+((size_t)b*8+c2)*HWD;  wt=qkw+c2*9; bias=qkb[c2]; dst=g_kk+((size_t)b*8+c2)*HWD; }
  else           { int c2=ch-16; src=g_v0+((size_t)b*64+c2)*HWD; wt=vw+c2*9;  bias=vb[c2];  dst=g_vv+((size_t)b*64+c2)*HWD; }
  int h=p>>6, w=p&63;
  float s=bias;
  #pragma unroll
  for (int kh=0;kh<3;kh++){
    int hh=h+kh-1;
    if (hh<0||hh>63) continue;
    #pragma unroll
    for (int kw2=0;kw2<3;kw2++){
      int ww=w+kw2-1;
      if (ww<0||ww>63) continue;
      s += wt[kh*3+kw2]*src[hh*64+ww];
    }
  }
  dst[p]=s;
}

// ---------------- attention: streamed softmax(QtK) applied to V ----------------
// block = (b, 64 queries); thread = (query, channel-group of 16)
// single-pass softmax without max (scores are tiny); packed f32x2 FMA over j-pairs
__global__ __launch_bounds__(256) void attn_kernel(){
  __shared__ float ks[8*128];
  __shared__ float vs[64*128];
  int b=blockIdx.y, tid=threadIdx.x;
  int ql=tid&63, cg=tid>>6;
  int i = blockIdx.x*64 + ql;
  const float* qb = g_qq + (size_t)b*8*HWD;
  const float* kb = g_kk + (size_t)b*8*HWD;
  const float* vb = g_vv + (size_t)b*CHW;
  u64 qdd[8];
  #pragma unroll
  for (int d=0;d<8;d++){ float qv=qb[d*HWD+i]; qdd[d]=pack2(qv,qv); }
  u64 acc[16];
  #pragma unroll
  for (int c=0;c<16;c++) acc[c]=0ULL;
  u64 l2=0ULL;
  for (int jt=0;jt<HWD;jt+=128){
    __syncthreads();
    for (int t=tid;t<8*128;t+=256){ int d=t>>7,j=t&127; ks[t]=kb[d*HWD+jt+j]; }
    for (int t=tid;t<64*128;t+=256){ int c=t>>7,j=t&127; vs[t]=vb[c*HWD+jt+j]; }
    __syncthreads();
    const float* vsc = vs + cg*16*128;
    #pragma unroll 2
    for (int jp=0;jp<64;jp++){
      u64 sa2=0ULL, sb2=0ULL;
      #pragma unroll
      for (int d=0;d<4;d++){
        sa2 = ffma2(qdd[d],   *reinterpret_cast<const u64*>(ks + d*128 + 2*jp), sa2);
        sb2 = ffma2(qdd[d+4], *reinterpret_cast<const u64*>(ks + (d+4)*128 + 2*jp), sb2);
      }
      u64 s2 = fadd2(sa2, sb2);
      float s0,s1; unpack2(s2,s0,s1);
      u64 e2 = pack2(__expf(s0), __expf(s1));
      l2 = fadd2(l2, e2);
      #pragma unroll
      for (int c=0;c<16;c++)
        acc[c] = ffma2(e2, *reinterpret_cast<const u64*>(vsc + c*128 + 2*jp), acc[c]);
    }
  }
  float la,lb; unpack2(l2,la,lb);
  float inv = 1.0f/(la+lb);
  float* ob = g_ao + (size_t)b*CHW + (size_t)cg*16*HWD;
  #pragma unroll
  for (int c=0;c<16;c++){
    float a0,a1; unpack2(acc[c],a0,a1);
    ob[c*HWD + i] = (a0+a1)*inv;
  }
}

// ---------------- proj 1x1 + gamma*y + xn ----------------
__global__ __launch_bounds__(256) void proj_kernel(
    const float* __restrict__ pw, const float* __restrict__ pb,
    const float* __restrict__ gm){
  __shared__ float ws[64*64];
  __shared__ float bs[64];
  __shared__ float xs[64*64];
  int b=blockIdx.y, p0=blockIdx.x*64, tid=threadIdx.x;
  for (int t=tid;t<4096;t+=256) ws[t]=pw[t];
  if (tid<64) bs[tid]=pb[tid];
  const float* ab = g_ao + (size_t)b*CHW + p0;
  for (int i=tid;i<4096;i+=256){int c=i>>6,p=i&63; xs[i]=ab[c*HWD+p];}
  __syncthreads();
  float g = gm[0];
  int og=tid>>6, p=tid&63;
  const float* xnb = g_xn + (size_t)b*CHW + p0;
  float* sb = g_sa + (size_t)b*CHW + p0;
  for (int r=0;r<16;r++){
    int o=og*16+r;
    float acc=bs[o];
    #pragma unroll
    for (int i=0;i<64;i++) acc += ws[o*64+i]*xs[i*64+p];
    sb[o*HWD+p] = g*acc + xnb[o*HWD+p];
  }
}

// ---------------- CAB conv1: 3x3 64->21 + GELU ----------------
__global__ __launch_bounds__(256) void cab1_kernel(
    const float* __restrict__ w1, const float* __restrict__ b1){
  __shared__ float ws[21*64*9];
  int tid=threadIdx.x;
  for (int t=tid;t<21*64*9;t+=256) ws[t]=w1[t];
  __syncthreads();
  int idx = blockIdx.x*256+tid;
  int wq = idx&15, h=(idx>>4)&63;
  int oc=(idx>>10)%21, b=(idx>>10)/21;
  int w0=wq*4;
  const float* xb = g_xn + (size_t)b*CHW;
  float acc[4];
  float bb=b1[oc];
  #pragma unroll
  for (int o=0;o<4;o++) acc[o]=bb;
  for (int ic=0;ic<64;ic++){
    const float* xc = xb + ic*HWD;
    float r0[6],r1[6],r2[6];
    #pragma unroll
    for (int dc=0;dc<6;dc++){
      int wwp=w0-1+dc;
      bool wok = (wwp>=0 && wwp<64);
      r0[dc] = (wok && h>0)  ? xc[(h-1)*64+wwp] : 0.f;
      r1[dc] = wok           ? xc[h*64+wwp]     : 0.f;
      r2[dc] = (wok && h<63) ? xc[(h+1)*64+wwp] : 0.f;
    }
    const float* wk = ws + (oc*64+ic)*9;
    #pragma unroll
    for (int o=0;o<4;o++){
      acc[o] += wk[0]*r0[o]+wk[1]*r0[o+1]+wk[2]*r0[o+2]
              + wk[3]*r1[o]+wk[4]*r1[o+1]+wk[5]*r1[o+2]
              + wk[6]*r2[o]+wk[7]*r2[o+1]+wk[8]*r2[o+2];
    }
  }
  float* ob = g_c1 + ((size_t)b*21+oc)*HWD + h*64 + w0;
  #pragma unroll
  for (int o=0;o<4;o++) ob[o]=gelu_f(acc[o]);
}

// ---------------- CAB conv2: 3x3 21->64 ----------------
__global__ __launch_bounds__(256) void cab2_kernel(
    const float* __restrict__ w2, const float* __restrict__ b2){
  __shared__ float ws[64*21*9];
  int tid=threadIdx.x;
  for (int t=tid;t<64*21*9;t+=256) ws[t]=w2[t];
  __syncthreads();
  int idx = blockIdx.x*256+tid;
  int wq = idx&15, h=(idx>>4)&63;
  int oc=(idx>>10)&63, b=idx>>16;
  int w0=wq*4;
  const float* xb = g_c1 + (size_t)b*21*HWD;
  float acc[4];
  float bb=b2[oc];
  #pragma unroll
  for (int o=0;o<4;o++) acc[o]=bb;
  for (int ic=0;ic<21;ic++){
    const float* xc = xb + ic*HWD;
    float r0[6],r1[6],r2[6];
    #pragma unroll
    for (int dc=0;dc<6;dc++){
      int wwp=w0-1+dc;
      bool wok = (wwp>=0 && wwp<64);
      r0[dc] = (wok && h>0)  ? xc[(h-1)*64+wwp] : 0.f;
      r1[dc] = wok           ? xc[h*64+wwp]     : 0.f;
      r2[dc] = (wok && h<63) ? xc[(h+1)*64+wwp] : 0.f;
    }
    const float* wk = ws + (oc*21+ic)*9;
    #pragma unroll
    for (int o=0;o<4;o++){
      acc[o] += wk[0]*r0[o]+wk[1]*r0[o+1]+wk[2]*r0[o+2]
              + wk[3]*r1[o]+wk[4]*r1[o+1]+wk[5]*r1[o+2]
              + wk[6]*r2[o]+wk[7]*r2[o+1]+wk[8]*r2[o+2];
    }
  }
  float* ob = g_cy + ((size_t)b*64+oc)*HWD + h*64 + w0;
  #pragma unroll
  for (int o=0;o<4;o++) ob[o]=acc[o];
}

// ---------------- global avg pool over HW ----------------
__global__ __launch_bounds__(256) void pool_kernel(){
  __shared__ float red[8];
  int c=blockIdx.x, b=blockIdx.y, tid=threadIdx.x;
  const float* src = g_cy + ((size_t)b*64+c)*HWD;
  float s=0.f;
  for (int i=tid;i<4096;i+=256) s+=src[i];
  #pragma unroll
  for (int o=16;o>0;o>>=1) s += __shfl_down_sync(0xffffffffu, s, o);
  if ((tid&31)==0) red[tid>>5]=s;
  __syncthreads();
  if (tid==0){
    float t=0.f;
    #pragma unroll
    for (int w2=0;w2<8;w2++) t+=red[w2];
    g_pool[b*64+c]=t*(1.f/4096.f);
  }
}

// ---------------- channel attention (64->2 relu, 2->64 sigmoid) ----------------
__global__ void ca_kernel(const float* __restrict__ w1, const float* __restrict__ b1,
                          const float* __restrict__ w2, const float* __restrict__ b2){
  int b=blockIdx.x, c=threadIdx.x;
  float z0=b1[0], z1=b1[1];
  for (int i=0;i<64;i++){
    float pv=g_pool[b*64+i];
    z0 += w1[i]*pv;
    z1 += w1[64+i]*pv;
  }
  z0 = fmaxf(z0,0.f); z1 = fmaxf(z1,0.f);
  float t = b2[c] + w2[c*2]*z0 + w2[c*2+1]*z1;
  g_pm[b*64+c] = 1.f/(1.f+__expf(-t));
}

// ---------------- feat_sum = sa_feat + y*p + x ----------------
__global__ __launch_bounds__(256) void fsum_kernel(const float* __restrict__ x){
  int i = (blockIdx.x*256+threadIdx.x)*4;
  int c=(i>>12)&63, b=i>>18;
  float pm = g_pm[b*64+c];
  float4 sa = *reinterpret_cast<const float4*>(g_sa+i);
  float4 cy = *reinterpret_cast<const float4*>(g_cy+i);
  float4 xx = *reinterpret_cast<const float4*>(x+i);
  float4 r;
  r.x = sa.x + cy.x*pm + xx.x;
  r.y = sa.y + cy.y*pm + xx.y;
  r.z = sa.z + cy.z*pm + xx.z;
  r.w = sa.w + cy.w*pm + xx.w;
  *reinterpret_cast<float4*>(g_fs+i)=r;
}

// ---------------- MLP: LN -> fc1+GELU -> fc2 -> reshape-add ----------------
__global__ __launch_bounds__(256) void mlp_kernel(
    const float* __restrict__ lnw, const float* __restrict__ lnb,
    const float* __restrict__ w1, const float* __restrict__ b1,
    const float* __restrict__ w2, const float* __restrict__ b2,
    float* __restrict__ out){
  __shared__ float xs[64*64];     // [c][p]; later reused (swizzled) for fc2 result
  __shared__ float hs[128*64];    // mu/rs temporarily in hs[0..127], then fc1 output
  int b=blockIdx.y, p0=blockIdx.x*64, tid=threadIdx.x;
  const size_t base = (size_t)b*CHW;
  for (int i=tid;i<4096;i+=256){int c=i>>6,p=i&63; xs[i]=g_fs[base + (size_t)c*HWD + p0+p];}
  __syncthreads();
  if (tid<64){
    float s=0.f,s2=0.f;
    #pragma unroll
    for (int c=0;c<64;c++){float v=xs[c*64+tid]; s+=v; s2+=v*v;}
    float m=s*(1.f/64.f);
    hs[tid]=m; hs[64+tid]=rsqrtf(s2*(1.f/64.f)-m*m+1e-5f);
  }
  __syncthreads();
  for (int i=tid;i<4096;i+=256){int c=i>>6,p=i&63;
    xs[i] = (xs[i]-hs[p])*hs[64+p]*lnw[c]+lnb[c];}
  __syncthreads();
  int og=tid>>6, p=tid&63;
  for (int r=0;r<32;r++){
    int o=og*32+r;
    float acc=b1[o];
    #pragma unroll
    for (int i2=0;i2<64;i2++) acc += w1[o*64+i2]*xs[i2*64+p];
    hs[o*64+p] = gelu_f(acc);
  }
  __syncthreads();
  for (int r=0;r<16;r++){
    int ch=og*16+r;
    float acc=b2[ch];
    #pragma unroll
    for (int i2=0;i2<128;i2++) acc += w2[ch*128+i2]*hs[i2*64+p];
    xs[ch*64 + ((p+ch)&63)] = acc;   // swizzle for conflict-free transposed read
  }
  __syncthreads();
  float* ob = out + base;
  const float* fb = g_fs + base;
  for (int i=tid;i<4096;i+=256){
    int pp=i>>6, ch=i&63;
    int f = (p0+pp)*64 + ch;         // raw-view reshape: t[pixel][ch] lands at flat p*64+ch
    ob[f] = xs[ch*64 + ((pp+ch)&63)] + fb[f];
  }
}

// ---------------- launch ----------------
extern "C" void kernel_launch(void* const* d_in, const int* in_sizes, int n_in,
                              void* d_out, int out_size){
  const float* x       = (const float*)d_in[0];
  const float* ln_w    = (const float*)d_in[1];
  const float* ln_b    = (const float*)d_in[2];
  const float* qw      = (const float*)d_in[3];
  const float* qb      = (const float*)d_in[4];
  const float* kw      = (const float*)d_in[5];
  const float* kb      = (const float*)d_in[6];
  const float* vw      = (const float*)d_in[7];
  const float* vb      = (const float*)d_in[8];
  const float* qkdw_w  = (const float*)d_in[9];
  const float* qkdw_b  = (const float*)d_in[10];
  const float* vdw_w   = (const float*)d_in[11];
  const float* vdw_b   = (const float*)d_in[12];
  const float* proj_w  = (const float*)d_in[13];
  const float* proj_b  = (const float*)d_in[14];
  const float* gamma   = (const float*)d_in[15];
  const float* cab_w1  = (const float*)d_in[16];
  const float* cab_b1  = (const float*)d_in[17];
  const float* cab_w2  = (const float*)d_in[18];
  const float* cab_b2  = (const float*)d_in[19];
  const float* ca_w1   = (const float*)d_in[20];
  const float* ca_b1   = (const float*)d_in[21];
  const float* ca_w2   = (const float*)d_in[22];
  const float* ca_b2   = (const float*)d_in[23];
  const float* fc1_w   = (const float*)d_in[24];
  const float* fc1_b   = (const float*)d_in[25];
  const float* fc2_w   = (const float*)d_in[26];
  const float* fc2_b   = (const float*)d_in[27];
  float* out = (float*)d_out;

  dim3 g64(64,4);
  ln_kernel  <<<g64,256>>>(x, ln_w, ln_b);
  qkv_kernel <<<g64,256>>>(qw,qb,kw,kb,vw,vb);
  dw_kernel  <<<5120,256>>>(qkdw_w,qkdw_b,vdw_w,vdw_b);
  cab1_kernel<<<336,256>>>(cab_w1,cab_b1);
  cab2_kernel<<<1024,256>>>(cab_w2,cab_b2);
  attn_kernel<<<g64,256>>>();
  proj_kernel<<<g64,256>>>(proj_w,proj_b,gamma);
  pool_kernel<<<g64,256>>>();
  ca_kernel  <<<4,64>>>(ca_w1,ca_b1,ca_w2,ca_b2);
  fsum_kernel<<<1024,256>>>(x);
  mlp_kernel <<<g64,256>>>(ln_w,ln_b,fc1_w,fc1_b,fc2_w,fc2_b,out);
}

// round 5
// speedup vs baseline: 1.2492x; 1.2492x over previous
#include <cuda_runtime.h>
#include <math.h>

#define BATCH 4
#define CDIM  64
#define HWD   4096
#define CHW   (CDIM*HWD)

typedef unsigned long long u64;

// ---------------- scratch (device globals; no allocation allowed) ----------------
__device__ __align__(16) float g_xn[BATCH*CHW];
__device__ __align__(16) float g_q0[BATCH*8*HWD];
__device__ __align__(16) float g_k0[BATCH*8*HWD];
__device__ __align__(16) float g_v0[BATCH*CHW];
__device__ __align__(16) float g_qq[BATCH*8*HWD];
__device__ __align__(16) float g_kk[BATCH*8*HWD];
__device__ __align__(16) float g_vv[BATCH*CHW];
__device__ __align__(16) float g_ao[BATCH*CHW];
__device__ __align__(16) float g_sa[BATCH*CHW];
__device__ __align__(16) float g_c1[BATCH*21*HWD];
__device__ __align__(16) float g_cy[BATCH*CHW];
__device__ float g_pool[BATCH*CDIM];
__device__ float g_pm[BATCH*CDIM];
__device__ __align__(16) float g_fs[BATCH*CHW];

// ---------------- helpers ----------------
__device__ __forceinline__ u64 pack2(float lo, float hi){
  u64 r; asm("mov.b64 %0,{%1,%2};" : "=l"(r) : "f"(lo), "f"(hi)); return r;
}
__device__ __forceinline__ void unpack2(u64 v, float& lo, float& hi){
  asm("mov.b64 {%0,%1},%2;" : "=f"(lo), "=f"(hi) : "l"(v));
}
__device__ __forceinline__ u64 ffma2(u64 a, u64 b, u64 c){
  u64 d; asm("fma.rn.f32x2 %0,%1,%2,%3;" : "=l"(d) : "l"(a), "l"(b), "l"(c)); return d;
}
__device__ __forceinline__ u64 fadd2(u64 a, u64 b){
  u64 d; asm("add.rn.f32x2 %0,%1,%2;" : "=l"(d) : "l"(a), "l"(b)); return d;
}
__device__ __forceinline__ float gelu_f(float x){
  return 0.5f*x*(1.0f + erff(x*0.7071067811865476f));
}

// load 6 contiguous taps [w0-1 .. w0+4] of row hh via one float4 + shuffles
__device__ __forceinline__ void row6(const float* __restrict__ xc, int hh, int w0, int wq, float* r){
  float4 v;
  if (hh>=0 && hh<64) v = *(const float4*)(xc + hh*64 + w0);
  else { v.x=0.f; v.y=0.f; v.z=0.f; v.w=0.f; }
  float lw = __shfl_up_sync(0xffffffffu, v.w, 1);
  float rx = __shfl_down_sync(0xffffffffu, v.x, 1);
  r[0] = (wq==0)?0.f:lw;
  r[1]=v.x; r[2]=v.y; r[3]=v.z; r[4]=v.w;
  r[5] = (wq==15)?0.f:rx;
}

// ---------------- LayerNorm over channel dim (per pixel) ----------------
__global__ __launch_bounds__(256) void ln_kernel(const float* __restrict__ x,
    const float* __restrict__ w, const float* __restrict__ bia){
  __shared__ float xs[64*64];
  __shared__ float mu[64], rs[64];
  int b = blockIdx.y, p0 = blockIdx.x*64, tid = threadIdx.x;
  const float* xb = x + (size_t)b*CHW + p0;
  for (int i=tid;i<4096;i+=256){int c=i>>6,p=i&63; xs[i]=xb[c*HWD+p];}
  __syncthreads();
  if (tid<64){
    float s=0.f,s2=0.f;
    #pragma unroll
    for (int c=0;c<64;c++){float v=xs[c*64+tid]; s+=v; s2+=v*v;}
    float m=s*(1.f/64.f);
    mu[tid]=m; rs[tid]=rsqrtf(s2*(1.f/64.f)-m*m+1e-5f);
  }
  __syncthreads();
  float* ob = g_xn + (size_t)b*CHW + p0;
  for (int i=tid;i<4096;i+=256){int c=i>>6,p=i&63;
    ob[c*HWD+p]=(xs[i]-mu[p])*rs[p]*w[c]+bia[c];}
}

// ---------------- fused q/k/v 1x1 convs (80 out ch), f32x2 pixel-quads ----------------
__global__ __launch_bounds__(256) void qkv_kernel(
    const float* __restrict__ qw, const float* __restrict__ qb,
    const float* __restrict__ kw, const float* __restrict__ kb,
    const float* __restrict__ vw, const float* __restrict__ vb){
  __shared__ float ws[80*64];
  __shared__ float bs[80];
  __shared__ float xs[64*64];
  int b = blockIdx.y, p0 = blockIdx.x*64, tid = threadIdx.x;
  for (int t=tid;t<80*64;t+=256){
    int o=t>>6, i=t&63;
    ws[t] = (o<8)? qw[o*64+i] : (o<16)? kw[(o-8)*64+i] : vw[(o-16)*64+i];
  }
  if (tid<80) bs[tid] = (tid<8)? qb[tid] : (tid<16)? kb[tid-8] : vb[tid-16];
  const float* xb = g_xn + (size_t)b*CHW + p0;
  for (int i=tid;i<4096;i+=256){int c=i>>6,p=i&63; xs[i]=xb[c*HWD+p];}
  __syncthreads();
  int pq = tid&15, og = tid>>4;
  int p4 = pq*4;
  for (int r=0;r<5;r++){
    int o = og*5+r;
    float bb = bs[o];
    u64 a0 = pack2(bb,bb), a1 = a0;
    const float* wo = ws + o*64;
    #pragma unroll
    for (int i=0;i<64;i++){
      float wv = wo[i];
      u64 w2 = pack2(wv,wv);
      const float* xp = xs + i*64 + p4;
      a0 = ffma2(w2, *(const u64*)(xp), a0);
      a1 = ffma2(w2, *(const u64*)(xp+2), a1);
    }
    float4 res;
    unpack2(a0,res.x,res.y); unpack2(a1,res.z,res.w);
    float* dst = (o<8)? (g_q0 + ((size_t)b*8+o)*HWD)
               : (o<16)? (g_k0 + ((size_t)b*8+(o-8))*HWD)
               : (g_v0 + ((size_t)b*64+(o-16))*HWD);
    *(float4*)(dst + p0 + p4) = res;
  }
}

// ---------------- depthwise 3x3 (q:8, k:8, v:64 channels) ----------------
__global__ __launch_bounds__(256) void dw_kernel(
    const float* __restrict__ qkw, const float* __restrict__ qkb,
    const float* __restrict__ vw, const float* __restrict__ vb){
  int idx = blockIdx.x*256 + threadIdx.x;
  int p  = idx & 4095;
  int ch = (idx>>12) % 80;
  int b  = (idx>>12) / 80;
  const float* src; const float* wt; float bias; float* dst;
  if (ch<8){ src=g_q0+((size_t)b*8+ch)*HWD;  wt=qkw+ch*9;      bias=qkb[ch];     dst=g_qq+((size_t)b*8+ch)*HWD; }
  else if (ch<16){ int c2=ch-8;  src=g_k0+((size_t)b*8+c2)*HWD;  wt=qkw+c2*9; bias=qkb[c2]; dst=g_kk+((size_t)b*8+c2)*HWD; }
  else           { int c2=ch-16; src=g_v0+((size_t)b*64+c2)*HWD; wt=vw+c2*9;  bias=vb[c2];  dst=g_vv+((size_t)b*64+c2)*HWD; }
  int h=p>>6, w=p&63;
  float s=bias;
  #pragma unroll
  for (int kh=0;kh<3;kh++){
    int hh=h+kh-1;
    if (hh<0||hh>63) continue;
    #pragma unroll
    for (int kw2=0;kw2<3;kw2++){
      int ww=w+kw2-1;
      if (ww<0||ww>63) continue;
      s += wt[kh*3+kw2]*src[hh*64+ww];
    }
  }
  dst[p]=s;
}

// ---------------- attention v2: dedup scores + f32x2/LDS.128 ----------------
// dyn smem: ks[8*128] | vs[64*128] | es[64*132] | ls[256]
#define ATTN_SMEM ((1024 + 8192 + 64*132 + 256)*4)
__global__ __launch_bounds__(256,2) void attn_kernel(){
  extern __shared__ float sm[];
  float* ks = sm;
  float* vs = sm + 1024;
  float* es = sm + 1024 + 8192;
  float* ls = es + 64*132;
  int b=blockIdx.y, tid=threadIdx.x;
  int il = tid&63, g = tid>>6;
  int i = blockIdx.x*64+il;
  const float* qb = g_qq + (size_t)b*8*HWD;
  const float* kb = g_kk + (size_t)b*8*HWD;
  const float* vb = g_vv + (size_t)b*CHW;
  u64 qdd[8];
  #pragma unroll
  for (int d=0;d<8;d++){ float qv=qb[d*HWD+i]; qdd[d]=pack2(qv,qv); }
  u64 acc[16];
  #pragma unroll
  for (int c=0;c<16;c++) acc[c]=0ULL;
  float lsum = 0.f;
  float* erow = es + il*132;
  const float* vsc = vs + g*16*128;
  int j0 = g*32;
  int kd = tid>>5, kj = (tid&31)*4;
  for (int jt=0;jt<HWD;jt+=128){
    __syncthreads();
    *(float4*)(ks + kd*128 + kj) = *(const float4*)(kb + kd*HWD + jt + kj);
    #pragma unroll
    for (int rr=0;rr<8;rr++){
      int t = tid + rr*256;
      int c = t>>5, jq = (t&31)*4;
      *(float4*)(vs + c*128 + jq) = *(const float4*)(vb + (size_t)c*HWD + jt + jq);
    }
    __syncthreads();
    // phase 1: scores + exp for this thread's 32-j slice
    #pragma unroll
    for (int j4=0;j4<32;j4+=4){
      int j = j0+j4;
      u64 s01=0ULL, s23=0ULL;
      #pragma unroll
      for (int d=0;d<8;d++){
        float4 kv = *(const float4*)(ks + d*128 + j);
        s01 = ffma2(qdd[d], pack2(kv.x,kv.y), s01);
        s23 = ffma2(qdd[d], pack2(kv.z,kv.w), s23);
      }
      float s0,s1,s2,s3;
      unpack2(s01,s0,s1); unpack2(s23,s2,s3);
      float4 ev;
      ev.x=__expf(s0); ev.y=__expf(s1); ev.z=__expf(s2); ev.w=__expf(s3);
      lsum += (ev.x+ev.y)+(ev.z+ev.w);
      *(float4*)(erow + j) = ev;
    }
    __syncthreads();
    // phase 2: O += e * v over all 128 j, 16 channels
    #pragma unroll 4
    for (int j4=0;j4<128;j4+=4){
      u64 e01 = *(const u64*)(erow + j4);
      u64 e23 = *(const u64*)(erow + j4 + 2);
      #pragma unroll
      for (int c=0;c<16;c++){
        const float* vr = vsc + c*128 + j4;
        acc[c] = ffma2(e01, *(const u64*)(vr), acc[c]);
        acc[c] = ffma2(e23, *(const u64*)(vr+2), acc[c]);
      }
    }
  }
  ls[g*64+il] = lsum;
  __syncthreads();
  float inv = 1.f/(ls[il]+ls[64+il]+ls[128+il]+ls[192+il]);
  float* ob = g_ao + (size_t)b*CHW + (size_t)g*16*HWD;
  #pragma unroll
  for (int c=0;c<16;c++){
    float a0,a1; unpack2(acc[c],a0,a1);
    ob[c*HWD + i] = (a0+a1)*inv;
  }
}

// ---------------- proj 1x1 + gamma*y + xn, f32x2 pixel-quads ----------------
__global__ __launch_bounds__(256) void proj_kernel(
    const float* __restrict__ pw, const float* __restrict__ pb,
    const float* __restrict__ gm){
  __shared__ float ws[64*64];
  __shared__ float bs[64];
  __shared__ float xs[64*64];
  int b=blockIdx.y, p0=blockIdx.x*64, tid=threadIdx.x;
  for (int t=tid;t<4096;t+=256) ws[t]=pw[t];
  if (tid<64) bs[tid]=pb[tid];
  const float* ab = g_ao + (size_t)b*CHW + p0;
  for (int i=tid;i<4096;i+=256){int c=i>>6,p=i&63; xs[i]=ab[c*HWD+p];}
  __syncthreads();
  float gmv = gm[0];
  int pq = tid&15, og = tid>>4;
  int p4 = pq*4;
  const float* xnb = g_xn + (size_t)b*CHW + p0;
  float* sb = g_sa + (size_t)b*CHW + p0;
  for (int r=0;r<4;r++){
    int o = og*4+r;
    float bb = bs[o];
    u64 a0 = pack2(bb,bb), a1 = a0;
    const float* wo = ws + o*64;
    #pragma unroll
    for (int i=0;i<64;i++){
      float wv = wo[i];
      u64 w2 = pack2(wv,wv);
      const float* xp = xs + i*64 + p4;
      a0 = ffma2(w2, *(const u64*)(xp), a0);
      a1 = ffma2(w2, *(const u64*)(xp+2), a1);
    }
    float f0,f1,f2,f3; unpack2(a0,f0,f1); unpack2(a1,f2,f3);
    float4 xn4 = *(const float4*)(xnb + o*HWD + p4);
    float4 res;
    res.x = gmv*f0 + xn4.x; res.y = gmv*f1 + xn4.y;
    res.z = gmv*f2 + xn4.z; res.w = gmv*f3 + xn4.w;
    *(float4*)(sb + o*HWD + p4) = res;
  }
}

// ---------------- CAB conv1: 3x3 64->21 + GELU (3 oc x 4 px / thread) ----------------
__global__ __launch_bounds__(256) void cab1_kernel(
    const float* __restrict__ w1, const float* __restrict__ b1){
  __shared__ float ws[64*28];   // [ic][3oc*9], row stride 28 (16B aligned)
  __shared__ float bs[3];
  int bx = blockIdx.x;
  int b = bx/28, rem = bx%28, ocg = rem>>2, hb = rem&3;
  int oc0 = ocg*3;
  int tid = threadIdx.x;
  for (int t=tid;t<64*27;t+=256){
    int ic=t/27, r=t%27, oo=r/9, k=r%9;
    ws[ic*28 + r] = w1[(oc0+oo)*576 + ic*9 + k];
  }
  if (tid<3) bs[tid]=b1[oc0+tid];
  __syncthreads();
  int wq = tid&15, hl = tid>>4;
  int h = hb*16 + hl, w0 = wq*4;
  const float* xb = g_xn + (size_t)b*CHW;
  float acc[3][4];
  #pragma unroll
  for (int oo=0;oo<3;oo++){
    float bb=bs[oo];
    #pragma unroll
    for (int o=0;o<4;o++) acc[oo][o]=bb;
  }
  for (int ic=0;ic<64;ic++){
    const float* xc = xb + ic*HWD;
    float r0[6],r1[6],r2[6];
    row6(xc, h-1, w0, wq, r0);
    row6(xc, h  , w0, wq, r1);
    row6(xc, h+1, w0, wq, r2);
    const float* wk = ws + ic*28;
    #pragma unroll
    for (int oo=0;oo<3;oo++){
      const float* wo = wk + oo*9;
      #pragma unroll
      for (int o=0;o<4;o++){
        acc[oo][o] += wo[0]*r0[o]+wo[1]*r0[o+1]+wo[2]*r0[o+2]
                    + wo[3]*r1[o]+wo[4]*r1[o+1]+wo[5]*r1[o+2]
                    + wo[6]*r2[o]+wo[7]*r2[o+1]+wo[8]*r2[o+2];
      }
    }
  }
  #pragma unroll
  for (int oo=0;oo<3;oo++){
    float4 res;
    res.x=gelu_f(acc[oo][0]); res.y=gelu_f(acc[oo][1]);
    res.z=gelu_f(acc[oo][2]); res.w=gelu_f(acc[oo][3]);
    *(float4*)(g_c1 + ((size_t)b*21+oc0+oo)*HWD + h*64 + w0) = res;
  }
}

// ---------------- CAB conv2: 3x3 21->64 (4 oc x 4 px / thread) ----------------
__global__ __launch_bounds__(256) void cab2_kernel(
    const float* __restrict__ w2, const float* __restrict__ b2){
  __shared__ float ws[21*40];   // [ic][4oc*9], row stride 40 (16B aligned)
  __shared__ float bs[4];
  int bx = blockIdx.x;
  int hb = bx&3, ocg = (bx>>2)&15, b = bx>>6;
  int oc0 = ocg*4;
  int tid = threadIdx.x;
  for (int t=tid;t<21*36;t+=256){
    int ic=t/36, r=t%36, oo=r/9, k=r%9;
    ws[ic*40 + r] = w2[(oc0+oo)*189 + ic*9 + k];
  }
  if (tid<4) bs[tid]=b2[oc0+tid];
  __syncthreads();
  int wq = tid&15, hl = tid>>4;
  int h = hb*16 + hl, w0 = wq*4;
  const float* xb = g_c1 + (size_t)b*21*HWD;
  float acc[4][4];
  #pragma unroll
  for (int oo=0;oo<4;oo++){
    float bb=bs[oo];
    #pragma unroll
    for (int o=0;o<4;o++) acc[oo][o]=bb;
  }
  for (int ic=0;ic<21;ic++){
    const float* xc = xb + ic*HWD;
    float r0[6],r1[6],r2[6];
    row6(xc, h-1, w0, wq, r0);
    row6(xc, h  , w0, wq, r1);
    row6(xc, h+1, w0, wq, r2);
    const float* wk = ws + ic*40;
    #pragma unroll
    for (int oo=0;oo<4;oo++){
      const float* wo = wk + oo*9;
      #pragma unroll
      for (int o=0;o<4;o++){
        acc[oo][o] += wo[0]*r0[o]+wo[1]*r0[o+1]+wo[2]*r0[o+2]
                    + wo[3]*r1[o]+wo[4]*r1[o+1]+wo[5]*r1[o+2]
                    + wo[6]*r2[o]+wo[7]*r2[o+1]+wo[8]*r2[o+2];
      }
    }
  }
  #pragma unroll
  for (int oo=0;oo<4;oo++){
    float4 res;
    res.x=acc[oo][0]; res.y=acc[oo][1]; res.z=acc[oo][2]; res.w=acc[oo][3];
    *(float4*)(g_cy + ((size_t)b*64+oc0+oo)*HWD + h*64 + w0) = res;
  }
}

// ---------------- global avg pool over HW ----------------
__global__ __launch_bounds__(256) void pool_kernel(){
  __shared__ float red[8];
  int c=blockIdx.x, b=blockIdx.y, tid=threadIdx.x;
  const float* src = g_cy + ((size_t)b*64+c)*HWD;
  float s=0.f;
  for (int i=tid;i<4096;i+=256) s+=src[i];
  #pragma unroll
  for (int o=16;o>0;o>>=1) s += __shfl_down_sync(0xffffffffu, s, o);
  if ((tid&31)==0) red[tid>>5]=s;
  __syncthreads();
  if (tid==0){
    float t=0.f;
    #pragma unroll
    for (int w2=0;w2<8;w2++) t+=red[w2];
    g_pool[b*64+c]=t*(1.f/4096.f);
  }
}

// ---------------- channel attention (64->2 relu, 2->64 sigmoid) ----------------
__global__ void ca_kernel(const float* __restrict__ w1, const float* __restrict__ b1,
                          const float* __restrict__ w2, const float* __restrict__ b2){
  int b=blockIdx.x, c=threadIdx.x;
  float z0=b1[0], z1=b1[1];
  for (int i=0;i<64;i++){
    float pv=g_pool[b*64+i];
    z0 += w1[i]*pv;
    z1 += w1[64+i]*pv;
  }
  z0 = fmaxf(z0,0.f); z1 = fmaxf(z1,0.f);
  float t = b2[c] + w2[c*2]*z0 + w2[c*2+1]*z1;
  g_pm[b*64+c] = 1.f/(1.f+__expf(-t));
}

// ---------------- feat_sum = sa_feat + y*p + x ----------------
__global__ __launch_bounds__(256) void fsum_kernel(const float* __restrict__ x){
  int i = (blockIdx.x*256+threadIdx.x)*4;
  int c=(i>>12)&63, b=i>>18;
  float pm = g_pm[b*64+c];
  float4 sa = *reinterpret_cast<const float4*>(g_sa+i);
  float4 cy = *reinterpret_cast<const float4*>(g_cy+i);
  float4 xx = *reinterpret_cast<const float4*>(x+i);
  float4 r;
  r.x = sa.x + cy.x*pm + xx.x;
  r.y = sa.y + cy.y*pm + xx.y;
  r.z = sa.z + cy.z*pm + xx.z;
  r.w = sa.w + cy.w*pm + xx.w;
  *reinterpret_cast<float4*>(g_fs+i)=r;
}

// ---------------- MLP: LN -> fc1+GELU -> fc2 -> reshape-add (f32x2 quads) ----------------
__global__ __launch_bounds__(256) void mlp_kernel(
    const float* __restrict__ lnw, const float* __restrict__ lnb,
    const float* __restrict__ w1, const float* __restrict__ b1,
    const float* __restrict__ w2, const float* __restrict__ b2,
    float* __restrict__ out){
  __shared__ float xs[64*64];
  __shared__ float hs[128*64];
  int b=blockIdx.y, p0=blockIdx.x*64, tid=threadIdx.x;
  const size_t base = (size_t)b*CHW;
  for (int i=tid;i<4096;i+=256){int c=i>>6,p=i&63; xs[i]=g_fs[base + (size_t)c*HWD + p0+p];}
  __syncthreads();
  if (tid<64){
    float s=0.f,s2=0.f;
    #pragma unroll
    for (int c=0;c<64;c++){float v=xs[c*64+tid]; s+=v; s2+=v*v;}
    float m=s*(1.f/64.f);
    hs[tid]=m; hs[64+tid]=rsqrtf(s2*(1.f/64.f)-m*m+1e-5f);
  }
  __syncthreads();
  for (int i=tid;i<4096;i+=256){int c=i>>6,p=i&63;
    xs[i] = (xs[i]-hs[p])*hs[64+p]*lnw[c]+lnb[c];}
  __syncthreads();
  int pq = tid&15, og = tid>>4;
  int p4 = pq*4;
  for (int r=0;r<8;r++){
    int o = og*8+r;
    float bb = b1[o];
    u64 a0 = pack2(bb,bb), a1 = a0;
    const float* wo = w1 + o*64;
    #pragma unroll
    for (int i2=0;i2<64;i2++){
      float wv = wo[i2];
      u64 wv2 = pack2(wv,wv);
      const float* xp = xs + i2*64 + p4;
      a0 = ffma2(wv2, *(const u64*)(xp), a0);
      a1 = ffma2(wv2, *(const u64*)(xp+2), a1);
    }
    float f0,f1,f2,f3; unpack2(a0,f0,f1); unpack2(a1,f2,f3);
    float4 res;
    res.x=gelu_f(f0); res.y=gelu_f(f1); res.z=gelu_f(f2); res.w=gelu_f(f3);
    *(float4*)(hs + o*64 + p4) = res;
  }
  __syncthreads();
  for (int r=0;r<4;r++){
    int ch = og*4+r;
    float bb = b2[ch];
    u64 a0 = pack2(bb,bb), a1 = a0;
    const float* wo = w2 + ch*128;
    #pragma unroll
    for (int i2=0;i2<128;i2++){
      float wv = wo[i2];
      u64 wv2 = pack2(wv,wv);
      const float* hp = hs + i2*64 + p4;
      a0 = ffma2(wv2, *(const u64*)(hp), a0);
      a1 = ffma2(wv2, *(const u64*)(hp+2), a1);
    }
    float f0,f1,f2,f3; unpack2(a0,f0,f1); unpack2(a1,f2,f3);
    xs[ch*64 + ((p4+0+ch)&63)] = f0;   // swizzled for conflict-free transposed read
    xs[ch*64 + ((p4+1+ch)&63)] = f1;
    xs[ch*64 + ((p4+2+ch)&63)] = f2;
    xs[ch*64 + ((p4+3+ch)&63)] = f3;
  }
  __syncthreads();
  float* ob = out + base;
  const float* fb = g_fs + base;
  for (int i=tid;i<4096;i+=256){
    int pp=i>>6, ch=i&63;
    int f = (p0+pp)*64 + ch;           // raw-view reshape
    ob[f] = xs[ch*64 + ((pp+ch)&63)] + fb[f];
  }
}

// ---------------- launch ----------------
extern "C" void kernel_launch(void* const* d_in, const int* in_sizes, int n_in,
                              void* d_out, int out_size){
  const float* x       = (const float*)d_in[0];
  const float* ln_w    = (const float*)d_in[1];
  const float* ln_b    = (const float*)d_in[2];
  const float* qw      = (const float*)d_in[3];
  const float* qb      = (const float*)d_in[4];
  const float* kw      = (const float*)d_in[5];
  const float* kb      = (const float*)d_in[6];
  const float* vw      = (const float*)d_in[7];
  const float* vb      = (const float*)d_in[8];
  const float* qkdw_w  = (const float*)d_in[9];
  const float* qkdw_b  = (const float*)d_in[10];
  const float* vdw_w   = (const float*)d_in[11];
  const float* vdw_b   = (const float*)d_in[12];
  const float* proj_w  = (const float*)d_in[13];
  const float* proj_b  = (const float*)d_in[14];
  const float* gamma   = (const float*)d_in[15];
  const float* cab_w1  = (const float*)d_in[16];
  const float* cab_b1  = (const float*)d_in[17];
  const float* cab_w2  = (const float*)d_in[18];
  const float* cab_b2  = (const float*)d_in[19];
  const float* ca_w1   = (const float*)d_in[20];
  const float* ca_b1   = (const float*)d_in[21];
  const float* ca_w2   = (const float*)d_in[22];
  const float* ca_b2   = (const float*)d_in[23];
  const float* fc1_w   = (const float*)d_in[24];
  const float* fc1_b   = (const float*)d_in[25];
  const float* fc2_w   = (const float*)d_in[26];
  const float* fc2_b   = (const float*)d_in[27];
  float* out = (float*)d_out;

  cudaFuncSetAttribute(attn_kernel, cudaFuncAttributeMaxDynamicSharedMemorySize, ATTN_SMEM);

  dim3 g64(64,4);
  ln_kernel  <<<g64,256>>>(x, ln_w, ln_b);
  qkv_kernel <<<g64,256>>>(qw,qb,kw,kb,vw,vb);
  dw_kernel  <<<5120,256>>>(qkdw_w,qkdw_b,vdw_w,vdw_b);
  cab1_kernel<<<112,256>>>(cab_w1,cab_b1);
  cab2_kernel<<<256,256>>>(cab_w2,cab_b2);
  attn_kernel<<<g64,256,ATTN_SMEM>>>();
  proj_kernel<<<g64,256>>>(proj_w,proj_b,gamma);
  pool_kernel<<<g64,256>>>();
  ca_kernel  <<<4,64>>>(ca_w1,ca_b1,ca_w2,ca_b2);
  fsum_kernel<<<1024,256>>>(x);
  mlp_kernel <<<g64,256>>>(ln_w,ln_b,fc1_w,fc1_b,fc2_w,fc2_b,out);
}